// round 4
// baseline (speedup 1.0000x reference)
#include <cuda_runtime.h>

#define N_DATA 1024
#define D_IN   256
#define H_DIM  384
#define C_OUT  10
#define M_IND  128
#define NT_PTS 256
#define SCALE_K (1.0f/1024.0f)
#define JITTER_K 1e-3f
#define LPACK (M_IND*(M_IND+1)/2)

typedef unsigned long long ull;

// ---------------- device scratch ----------------
__device__ float g_HX[N_DATA*H_DIM];
__device__ float g_SX[N_DATA*H_DIM];
__device__ float g_HZ[M_IND*H_DIM];
__device__ float g_SZ[M_IND*H_DIM];
__device__ float g_HT[NT_PTS*H_DIM];
__device__ float g_ST[NT_PTS*H_DIM];
__device__ float g_LAM[N_DATA*C_OUT];
__device__ float g_Kzx[C_OUT*M_IND*N_DATA];
__device__ float g_Kzz[C_OUT*M_IND*M_IND];
__device__ float g_Ktz[C_OUT*NT_PTS*M_IND];
__device__ float g_Bpart[8*C_OUT*M_IND*M_IND];
__device__ float g_LKzz[C_OUT*LPACK];
__device__ float g_LB[C_OUT*LPACK];
__device__ float g_alpha[C_OUT*M_IND];
__device__ float g_cvec[C_OUT*M_IND];
__device__ float g_SSZ[C_OUT*NT_PTS];
__device__ float g_SSB[C_OUT*NT_PTS];

// ---------------- f32x2 packed helpers (FFMA2 path) ----------------
__device__ __forceinline__ ull dup2(float x) {
    ull r; unsigned u = __float_as_uint(x);
    asm("mov.b64 %0, {%1, %1};" : "=l"(r) : "r"(u));
    return r;
}
__device__ __forceinline__ void fma2(ull& d, ull a, ull b) {
    asm("fma.rn.f32x2 %0, %1, %2, %0;" : "+l"(d) : "l"(a), "l"(b));
}
__device__ __forceinline__ ull mul2(ull a, ull b) {
    ull d; asm("mul.rn.f32x2 %0, %1, %2;" : "=l"(d) : "l"(a), "l"(b));
    return d;
}
__device__ __forceinline__ float2 unp(ull v) {
    float2 f;
    asm("mov.b64 {%0, %1}, %2;" : "=f"(f.x), "=f"(f.y) : "l"(v));
    return f;
}

// =============== forward: H = tanh(In@W1+b1), S = 1-H^2 ===============
// grid (3, 22), 128 threads, tile 64m x 128n, 8x8 per thread via FFMA2
__global__ void __launch_bounds__(128, 4)
fwd_all(const float* __restrict__ X, const float* __restrict__ Z,
        const float* __restrict__ T, const float* __restrict__ W1,
        const float* __restrict__ b1) {
    __shared__ __align__(16) float As[16][68];
    __shared__ __align__(16) float Bs[16][132];
    const int tid = threadIdx.x;
    const int rb = blockIdx.y, nb = blockIdx.x;
    const float* src; float* Hd; float* Sd; int row0;
    if (rb < 16)      { src = X; Hd = g_HX; Sd = g_SX; row0 = rb*64; }
    else if (rb < 18) { src = Z; Hd = g_HZ; Sd = g_SZ; row0 = (rb-16)*64; }
    else              { src = T; Hd = g_HT; Sd = g_ST; row0 = (rb-18)*64; }
    const int n0b = nb*128;
    const int lr = tid >> 1, lq = (tid & 1) << 3;
    const int kr = tid >> 3, nq = (tid & 7) << 4;
    const int ty = tid >> 4, tx = tid & 15;
    ull acc[8][4] = {};
    for (int k0 = 0; k0 < D_IN; k0 += 16) {
        float4 a0 = *(const float4*)&src[(row0+lr)*D_IN + k0 + lq];
        float4 a1 = *(const float4*)&src[(row0+lr)*D_IN + k0 + lq + 4];
        float4 w0 = *(const float4*)&W1[(k0+kr)*H_DIM + n0b + nq];
        float4 w1 = *(const float4*)&W1[(k0+kr)*H_DIM + n0b + nq + 4];
        float4 w2 = *(const float4*)&W1[(k0+kr)*H_DIM + n0b + nq + 8];
        float4 w3 = *(const float4*)&W1[(k0+kr)*H_DIM + n0b + nq + 12];
        __syncthreads();
        As[lq+0][lr]=a0.x; As[lq+1][lr]=a0.y; As[lq+2][lr]=a0.z; As[lq+3][lr]=a0.w;
        As[lq+4][lr]=a1.x; As[lq+5][lr]=a1.y; As[lq+6][lr]=a1.z; As[lq+7][lr]=a1.w;
        *(float4*)&Bs[kr][nq]    = w0; *(float4*)&Bs[kr][nq+4]  = w1;
        *(float4*)&Bs[kr][nq+8]  = w2; *(float4*)&Bs[kr][nq+12] = w3;
        __syncthreads();
        #pragma unroll
        for (int kk = 0; kk < 16; ++kk) {
            float4 a4 = *(const float4*)&As[kk][ty*8];
            float4 a5 = *(const float4*)&As[kk][ty*8+4];
            ull b[4];
            #pragma unroll
            for (int v = 0; v < 4; ++v) b[v] = *(const ull*)&Bs[kk][tx*8 + v*2];
            float a[8] = {a4.x,a4.y,a4.z,a4.w,a5.x,a5.y,a5.z,a5.w};
            #pragma unroll
            for (int u = 0; u < 8; ++u) {
                ull du = dup2(a[u]);
                #pragma unroll
                for (int v = 0; v < 4; ++v) fma2(acc[u][v], du, b[v]);
            }
        }
    }
    const int n0 = n0b + tx*8;
    float4 bv0 = *(const float4*)&b1[n0];
    float4 bv1 = *(const float4*)&b1[n0+4];
    float bb[8] = {bv0.x,bv0.y,bv0.z,bv0.w,bv1.x,bv1.y,bv1.z,bv1.w};
    #pragma unroll
    for (int u = 0; u < 8; ++u) {
        int m = row0 + ty*8 + u;
        float h[8], s[8];
        #pragma unroll
        for (int v = 0; v < 4; ++v) {
            float2 p = unp(acc[u][v]);
            h[v*2]   = tanhf(p.x + bb[v*2]);
            h[v*2+1] = tanhf(p.y + bb[v*2+1]);
        }
        #pragma unroll
        for (int c = 0; c < 8; ++c) s[c] = 1.0f - h[c]*h[c];
        *(float4*)&Hd[m*H_DIM + n0]   = make_float4(h[0],h[1],h[2],h[3]);
        *(float4*)&Hd[m*H_DIM + n0+4] = make_float4(h[4],h[5],h[6],h[7]);
        *(float4*)&Sd[m*H_DIM + n0]   = make_float4(s[0],s[1],s[2],s[3]);
        *(float4*)&Sd[m*H_DIM + n0+4] = make_float4(s[4],s[5],s[6],s[7]);
    }
}

// =============== lambda1 = F + Y ===============
__global__ void lam_kernel(const float* __restrict__ Y, const float* __restrict__ W2,
                           const float* __restrict__ b2) {
    int warp = threadIdx.x >> 5, lane = threadIdx.x & 31;
    int row = blockIdx.x * 8 + warp;
    float h[12];
    #pragma unroll
    for (int r = 0; r < 12; ++r) h[r] = g_HX[row*H_DIM + lane + r*32];
    #pragma unroll
    for (int c = 0; c < C_OUT; ++c) {
        float acc = 0.f;
        #pragma unroll
        for (int r = 0; r < 12; ++r) acc += h[r] * W2[(lane + r*32)*C_OUT + c];
        #pragma unroll
        for (int o = 16; o; o >>= 1) acc += __shfl_down_sync(0xffffffffu, acc, o);
        if (lane == 0) g_LAM[row*C_OUT + c] = acc + b2[c] + Y[row*C_OUT + c];
    }
}

// =============== fused kernel builder: K_i for 5 outputs + P + Q per block ===============
// 176 blocks, 256 threads, tile 64m x 32n; per thread 4m x 2n(pair) x 5i + P + Q
__global__ void __launch_bounds__(256, 2)
kbuild_all(const float* __restrict__ X, const float* __restrict__ Z,
           const float* __restrict__ T, const float* __restrict__ W2) {
    __shared__ __align__(16) float SA[16][68];
    __shared__ __align__(16) float HA[16][68];
    __shared__ __align__(16) float SB[16][36];
    __shared__ __align__(16) float HB[16][36];
    __shared__ float WS[16][8];
    const int tid = threadIdx.x;
    int j = blockIdx.x;
    int g, mt, nt, jit = 0, Nc;
    const float *Sa, *Ha, *Xa, *Sb, *Hb, *Xb; float* Kbase; int KstrI;
    if (j < 128) {
        g = j >> 6; int r = j & 63; mt = r >> 5; nt = r & 31;
        Sa=g_SZ; Ha=g_HZ; Xa=Z; Sb=g_SX; Hb=g_HX; Xb=X;
        Kbase=g_Kzx; KstrI=M_IND*N_DATA; Nc=N_DATA;
    } else if (j < 144) {
        int r = j-128; g = r >> 3; mt = (r >> 2) & 1; nt = r & 3;
        Sa=g_SZ; Ha=g_HZ; Xa=Z; Sb=g_SZ; Hb=g_HZ; Xb=Z;
        Kbase=g_Kzz; KstrI=M_IND*M_IND; Nc=M_IND; jit=1;
    } else {
        int r = j-144; g = r >> 4; mt = (r >> 2) & 3; nt = r & 3;
        Sa=g_ST; Ha=g_HT; Xa=T; Sb=g_SZ; Hb=g_HZ; Xb=Z;
        Kbase=g_Ktz; KstrI=NT_PTS*M_IND; Nc=M_IND;
    }
    const int i0 = g*5;
    const int bm = mt*64, bn = nt*32;
    const int ty = tid >> 4, tx = tid & 15;
    const int lr = tid >> 2, lq = (tid & 3) << 2;        // 64-row loader
    const int sr = (tid & 127) >> 2, sq = (tid & 3) << 2; // 32-row loader
    ull accU[4][5] = {};
    ull accP[4] = {}, accQ[4] = {};
    // ---------- H-dim phase: P (h.h') and U_i ((s w_i^2).s') ----------
    for (int k0 = 0; k0 < H_DIM; k0 += 16) {
        float4 va = *(const float4*)&Sa[(bm+lr)*H_DIM + k0 + lq];
        float4 vh = *(const float4*)&Ha[(bm+lr)*H_DIM + k0 + lq];
        float4 vb;
        if (tid < 128) vb = *(const float4*)&Sb[(bn+sr)*H_DIM + k0 + sq];
        else           vb = *(const float4*)&Hb[(bn+sr)*H_DIM + k0 + sq];
        float wv = 0.f; int wk = 0, wi = 0;
        if (tid < 80) {
            wk = tid / 5; wi = tid - wk*5;
            float w = W2[(k0+wk)*C_OUT + i0 + wi];
            wv = w*w;
        }
        __syncthreads();
        SA[lq+0][lr]=va.x; SA[lq+1][lr]=va.y; SA[lq+2][lr]=va.z; SA[lq+3][lr]=va.w;
        HA[lq+0][lr]=vh.x; HA[lq+1][lr]=vh.y; HA[lq+2][lr]=vh.z; HA[lq+3][lr]=vh.w;
        if (tid < 128) { SB[sq+0][sr]=vb.x; SB[sq+1][sr]=vb.y; SB[sq+2][sr]=vb.z; SB[sq+3][sr]=vb.w; }
        else           { HB[sq+0][sr]=vb.x; HB[sq+1][sr]=vb.y; HB[sq+2][sr]=vb.z; HB[sq+3][sr]=vb.w; }
        if (tid < 80) WS[wk][wi] = wv;
        __syncthreads();
        #pragma unroll
        for (int kk = 0; kk < 16; ++kk) {
            float4 sa4 = *(const float4*)&SA[kk][ty*4];
            float4 ha4 = *(const float4*)&HA[kk][ty*4];
            ull sbp = *(const ull*)&SB[kk][tx*2];
            ull hbp = *(const ull*)&HB[kk][tx*2];
            ull wd[5];
            #pragma unroll
            for (int i = 0; i < 5; ++i) wd[i] = dup2(WS[kk][i]);
            float sa[4] = {sa4.x, sa4.y, sa4.z, sa4.w};
            float ha[4] = {ha4.x, ha4.y, ha4.z, ha4.w};
            #pragma unroll
            for (int u = 0; u < 4; ++u) {
                ull p2 = mul2(dup2(sa[u]), sbp);
                fma2(accP[u], dup2(ha[u]), hbp);
                #pragma unroll
                for (int i = 0; i < 5; ++i) fma2(accU[u][i], p2, wd[i]);
            }
        }
    }
    // ---------- D-dim phase: Q (x.x'), reuse SA/SB ----------
    for (int k0 = 0; k0 < D_IN; k0 += 16) {
        float4 va = *(const float4*)&Xa[(bm+lr)*D_IN + k0 + lq];
        float4 vb;
        if (tid < 128) vb = *(const float4*)&Xb[(bn+sr)*D_IN + k0 + sq];
        __syncthreads();
        SA[lq+0][lr]=va.x; SA[lq+1][lr]=va.y; SA[lq+2][lr]=va.z; SA[lq+3][lr]=va.w;
        if (tid < 128) { SB[sq+0][sr]=vb.x; SB[sq+1][sr]=vb.y; SB[sq+2][sr]=vb.z; SB[sq+3][sr]=vb.w; }
        __syncthreads();
        #pragma unroll
        for (int kk = 0; kk < 16; ++kk) {
            float4 xa4 = *(const float4*)&SA[kk][ty*4];
            ull xbp = *(const ull*)&SB[kk][tx*2];
            float xa[4] = {xa4.x, xa4.y, xa4.z, xa4.w};
            #pragma unroll
            for (int u = 0; u < 4; ++u) fma2(accQ[u], dup2(xa[u]), xbp);
        }
    }
    // ---------- epilogue: K_i = SCALE*((P+1) + (Q+1)*U_i) ----------
    const int n0 = bn + tx*2;
    #pragma unroll
    for (int u = 0; u < 4; ++u) {
        int m = bm + ty*4 + u;
        float2 p = unp(accP[u]);
        float2 q = unp(accQ[u]);
        float plo = p.x + 1.f, phi = p.y + 1.f;
        float qlo = q.x + 1.f, qhi = q.y + 1.f;
        #pragma unroll
        for (int i = 0; i < 5; ++i) {
            float2 uu = unp(accU[u][i]);
            float klo = SCALE_K * (plo + qlo*uu.x);
            float khi = SCALE_K * (phi + qhi*uu.y);
            if (jit) {
                if (m == n0)   klo += JITTER_K;
                if (m == n0+1) khi += JITTER_K;
            }
            *(float2*)&Kbase[(size_t)(i0+i)*KstrI + (size_t)m*Nc + n0] = make_float2(klo, khi);
        }
    }
}

// =============== Bpart (split-K=8 of 2*Kzx@Kzx^T) + alpha ===============
__global__ void __launch_bounds__(256, 2)
bgemm_alpha() {
    const int tid = threadIdx.x;
    const int j = blockIdx.x;
    if (j < 80) {
        __shared__ __align__(16) float As[16][132];
        const int i = j >> 3, kc = j & 7;
        const float* A = g_Kzx + (size_t)i*M_IND*N_DATA;
        const int kbeg = kc*128;
        const int lr = tid >> 1, lq = (tid & 1) << 3;
        const int ty = tid >> 4, tx = tid & 15;
        ull acc[8][4] = {};
        for (int k0 = kbeg; k0 < kbeg+128; k0 += 16) {
            float4 a0 = *(const float4*)&A[lr*N_DATA + k0 + lq];
            float4 a1 = *(const float4*)&A[lr*N_DATA + k0 + lq + 4];
            __syncthreads();
            As[lq+0][lr]=a0.x; As[lq+1][lr]=a0.y; As[lq+2][lr]=a0.z; As[lq+3][lr]=a0.w;
            As[lq+4][lr]=a1.x; As[lq+5][lr]=a1.y; As[lq+6][lr]=a1.z; As[lq+7][lr]=a1.w;
            __syncthreads();
            #pragma unroll
            for (int kk = 0; kk < 16; ++kk) {
                float4 a4 = *(const float4*)&As[kk][ty*8];
                float4 a5 = *(const float4*)&As[kk][ty*8+4];
                ull b[4];
                #pragma unroll
                for (int v = 0; v < 4; ++v) b[v] = *(const ull*)&As[kk][tx*8 + v*2];
                float a[8] = {a4.x,a4.y,a4.z,a4.w,a5.x,a5.y,a5.z,a5.w};
                #pragma unroll
                for (int u = 0; u < 8; ++u) {
                    ull du = dup2(a[u]);
                    #pragma unroll
                    for (int v = 0; v < 4; ++v) fma2(acc[u][v], du, b[v]);
                }
            }
        }
        float* outp = g_Bpart + (size_t)(kc*C_OUT + i)*M_IND*M_IND;
        const int n0 = tx*8;
        #pragma unroll
        for (int u = 0; u < 8; ++u) {
            int m = ty*8 + u;
            float o[8];
            #pragma unroll
            for (int v = 0; v < 4; ++v) {
                float2 pp = unp(acc[u][v]);
                o[v*2] = 2.f*pp.x; o[v*2+1] = 2.f*pp.y;
            }
            *(float4*)&outp[m*M_IND + n0]   = make_float4(o[0],o[1],o[2],o[3]);
            *(float4*)&outp[m*M_IND + n0+4] = make_float4(o[4],o[5],o[6],o[7]);
        }
    } else {
        const int k = j - 80;
        const int w = tid >> 5, lane = tid & 31;
        const int gw = k*8 + w;            // 0..159
        const int i = gw >> 4, rb = (gw & 15) * 8;
        #pragma unroll
        for (int rr = 0; rr < 8; ++rr) {
            int m = rb + rr;
            const float* row = g_Kzx + ((size_t)i*M_IND + m)*N_DATA;
            float acc = 0.f;
            for (int n = lane; n < N_DATA; n += 32) acc += row[n] * g_LAM[n*C_OUT + i];
            #pragma unroll
            for (int o = 16; o; o >>= 1) acc += __shfl_down_sync(0xffffffffu, acc, o);
            if (lane == 0) g_alpha[i*M_IND + m] = acc;
        }
    }
}

// =============== batched Cholesky of Kzz and B = Kzz + sum(Bpart) ===============
__global__ void chol_all() {
    const int s = blockIdx.x, tid = threadIdx.x;
    const int isB = (s >= C_OUT);
    const int i = isB ? s - C_OUT : s;
    const float* A0 = g_Kzz + (size_t)i*M_IND*M_IND;
    __shared__ float L[LPACK];
    __shared__ float s_diag;
    for (int r = 0; r < M_IND; ++r)
        for (int c = tid; c <= r; c += 256) {
            float v = A0[r*M_IND + c];
            if (isB) {
                #pragma unroll
                for (int p = 0; p < 8; ++p)
                    v += g_Bpart[((size_t)(p*C_OUT + i)*M_IND + r)*M_IND + c];
            }
            L[((r*(r+1))>>1) + c] = v;
        }
    __syncthreads();
    for (int jc = 0; jc < M_IND; ++jc) {
        int ir = jc + tid;
        float sum = 0.f;
        if (ir < M_IND) {
            const float* ri = &L[(ir*(ir+1)) >> 1];
            const float* rj = &L[(jc*(jc+1)) >> 1];
            float s0=0,s1=0,s2=0,s3=0; int k = 0;
            for (; k+4 <= jc; k += 4) {
                s0 += ri[k]*rj[k];     s1 += ri[k+1]*rj[k+1];
                s2 += ri[k+2]*rj[k+2]; s3 += ri[k+3]*rj[k+3];
            }
            for (; k < jc; ++k) s0 += ri[k]*rj[k];
            sum = ri[jc] - ((s0+s1)+(s2+s3));
            if (tid == 0) s_diag = sum;
        }
        __syncthreads();
        float d = sqrtf(s_diag);
        if (ir < M_IND) L[((ir*(ir+1))>>1) + jc] = (tid == 0) ? d : (sum / d);
        __syncthreads();
    }
    float* out = isB ? (g_LB + i*LPACK) : (g_LKzz + i*LPACK);
    for (int idx = tid; idx < LPACK; idx += 256) out[idx] = L[idx];
}

// =============== solves: 640 fs blocks + 10 meansolve blocks ===============
__global__ void solve_all() {
    __shared__ float Lp[LPACK];
    __shared__ float dinv[M_IND];
    __shared__ float ysm[M_IND];
    const int b = blockIdx.x, tid = threadIdx.x;
    const int w = tid >> 5, lane = tid & 31;
    if (b < 640) {
        const int s = b >> 5;
        const int t = (b & 31)*8 + w;
        const int i = (s < C_OUT) ? s : s - C_OUT;
        const float* Ls = (s < C_OUT) ? (g_LKzz + s*LPACK) : (g_LB + (s-C_OUT)*LPACK);
        for (int idx = tid; idx < LPACK; idx += 256) Lp[idx] = Ls[idx];
        if (tid < M_IND) dinv[tid] = 1.0f / Ls[((tid*(tid+1))>>1) + tid];
        __syncthreads();
        const float* bvec = g_Ktz + ((size_t)i*NT_PTS + t)*M_IND;
        float br[4]; int base[4];
        #pragma unroll
        for (int r = 0; r < 4; ++r) {
            br[r] = bvec[lane + 32*r];
            int row = r*32 + lane;
            base[r] = (row*(row+1)) >> 1;
        }
        float ss = 0.f;
        #pragma unroll
        for (int oreg = 0; oreg < 4; ++oreg) {
            for (int jj = 0; jj < 32; ++jj) {
                int jc = oreg*32 + jj;
                float yj = __shfl_sync(0xffffffffu, br[oreg], jj) * dinv[jc];
                ss = fmaf(yj, yj, ss);
                if (lane > jj) br[oreg] -= Lp[base[oreg] + jc] * yj;
                #pragma unroll
                for (int r = oreg+1; r < 4; ++r) br[r] -= Lp[base[r] + jc] * yj;
            }
        }
        if (lane == 0) {
            if (s < C_OUT) g_SSZ[i*NT_PTS + t] = ss;
            else           g_SSB[i*NT_PTS + t] = ss;
        }
    } else {
        const int i = b - 640;
        const float* Ls = g_LB + i*LPACK;
        for (int idx = tid; idx < LPACK; idx += 256) Lp[idx] = Ls[idx];
        if (tid < M_IND) dinv[tid] = 1.0f / Ls[((tid*(tid+1))>>1) + tid];
        __syncthreads();
        if (w != 0) return;
        float br[4]; int base[4];
        #pragma unroll
        for (int r = 0; r < 4; ++r) {
            br[r] = g_alpha[i*M_IND + lane + 32*r];
            int row = r*32 + lane;
            base[r] = (row*(row+1)) >> 1;
        }
        #pragma unroll
        for (int oreg = 0; oreg < 4; ++oreg) {
            for (int jj = 0; jj < 32; ++jj) {
                int jc = oreg*32 + jj;
                float yj = __shfl_sync(0xffffffffu, br[oreg], jj) * dinv[jc];
                if (lane == 0) ysm[jc] = yj;
                if (lane > jj) br[oreg] -= Lp[base[oreg] + jc] * yj;
                #pragma unroll
                for (int r = oreg+1; r < 4; ++r) br[r] -= Lp[base[r] + jc] * yj;
            }
        }
        __syncwarp();
        float xr[4];
        #pragma unroll
        for (int r = 0; r < 4; ++r) xr[r] = ysm[r*32 + lane];
        #pragma unroll
        for (int oreg = 3; oreg >= 0; --oreg) {
            for (int jj = 31; jj >= 0; --jj) {
                int jc = oreg*32 + jj;
                float xj = __shfl_sync(0xffffffffu, xr[oreg], jj) * dinv[jc];
                if (lane == 0) g_cvec[i*M_IND + jc] = xj;
                int rb2 = (jc*(jc+1)) >> 1;
                if (lane < jj) xr[oreg] -= Lp[rb2 + oreg*32 + lane] * xj;
                #pragma unroll
                for (int r = 0; r < 4; ++r)
                    if (r < oreg) xr[r] -= Lp[rb2 + r*32 + lane] * xj;
            }
        }
    }
}

// =============== epilogue: mean + variance ===============
__global__ void epilogue(const float* __restrict__ Xt, const float* __restrict__ W2,
                         float* __restrict__ out) {
    const int gw = blockIdx.x*8 + (threadIdx.x >> 5);
    const int lane = threadIdx.x & 31;
    const int t = gw / C_OUT, i = gw - t*C_OUT;
    float accU = 0.f, ph = 0.f, qx = 0.f;
    for (int k = lane; k < H_DIM; k += 32) {
        float s = g_ST[t*H_DIM + k];
        float h = g_HT[t*H_DIM + k];
        float w = W2[k*C_OUT + i];
        accU = fmaf(s*s, w*w, accU);
        ph = fmaf(h, h, ph);
    }
    for (int k = lane; k < D_IN; k += 32) { float x = Xt[t*D_IN + k]; qx = fmaf(x, x, qx); }
    float mean = 0.f;
    const float* kr = g_Ktz + ((size_t)i*NT_PTS + t)*M_IND;
    const float* cr = g_cvec + i*M_IND;
    #pragma unroll
    for (int r = 0; r < 4; ++r) mean += kr[lane + 32*r] * cr[lane + 32*r];
    #pragma unroll
    for (int o = 16; o; o >>= 1) {
        accU += __shfl_xor_sync(0xffffffffu, accU, o);
        ph   += __shfl_xor_sync(0xffffffffu, ph, o);
        qx   += __shfl_xor_sync(0xffffffffu, qx, o);
        mean += __shfl_xor_sync(0xffffffffu, mean, o);
    }
    if (lane == 0) {
        float kttd = SCALE_K * ((ph + 1.f) + (qx + 1.f)*accU);
        out[t*C_OUT + i] = mean;
        out[NT_PTS*C_OUT + t*C_OUT + i] = kttd - g_SSZ[i*NT_PTS + t] + g_SSB[i*NT_PTS + t];
    }
}

extern "C" void kernel_launch(void* const* d_in, const int* in_sizes, int n_in,
                              void* d_out, int out_size) {
    const float* X  = (const float*)d_in[0];
    const float* Y  = (const float*)d_in[1];
    const float* Z  = (const float*)d_in[2];
    const float* Xt = (const float*)d_in[3];
    const float* W1 = (const float*)d_in[4];
    const float* b1 = (const float*)d_in[5];
    const float* W2 = (const float*)d_in[6];
    const float* b2 = (const float*)d_in[7];
    float* out = (float*)d_out;

    fwd_all<<<dim3(3,22), 128>>>(X, Z, Xt, W1, b1);
    lam_kernel<<<128, 256>>>(Y, W2, b2);
    kbuild_all<<<176, 256>>>(X, Z, Xt, W2);
    bgemm_alpha<<<100, 256>>>();
    chol_all<<<20, 256>>>();
    solve_all<<<650, 256>>>();
    epilogue<<<320, 256>>>(Xt, W2, out);
}

// round 5
// speedup vs baseline: 1.0554x; 1.0554x over previous
#include <cuda_runtime.h>

#define N_DATA 1024
#define D_IN   256
#define H_DIM  384
#define C_OUT  10
#define M_IND  128
#define NT_PTS 256
#define NCAT   1408
#define SCALE_K (1.0f/1024.0f)
#define JITTER_K 1e-3f
#define LPACK (M_IND*(M_IND+1)/2)

typedef unsigned long long ull;

// ---------------- device scratch ----------------
__device__ float g_HX[N_DATA*H_DIM];
__device__ float g_SX[N_DATA*H_DIM];
__device__ float g_HZ[M_IND*H_DIM];
__device__ float g_SZ[M_IND*H_DIM];
__device__ float g_HT[NT_PTS*H_DIM];
__device__ float g_ST[NT_PTS*H_DIM];
__device__ float g_LAM[N_DATA*C_OUT];
__device__ float g_W2SQ[C_OUT*H_DIM];
__device__ float g_Pcat[M_IND*NCAT];
__device__ float g_Qcat[M_IND*NCAT];
__device__ float g_Kzx[C_OUT*M_IND*N_DATA];
__device__ float g_Kzz[C_OUT*M_IND*M_IND];
__device__ float g_Ktz[C_OUT*NT_PTS*M_IND];
__device__ float g_Bpart[8*C_OUT*M_IND*M_IND];
__device__ float g_LKzz[C_OUT*LPACK];
__device__ float g_LB[C_OUT*LPACK];
__device__ float g_alpha[C_OUT*M_IND];
__device__ float g_cvec[C_OUT*M_IND];
__device__ float g_SSZ[C_OUT*NT_PTS];
__device__ float g_SSB[C_OUT*NT_PTS];

// ---------------- f32x2 packed helpers ----------------
__device__ __forceinline__ ull dup2(float x) {
    ull r; unsigned u = __float_as_uint(x);
    asm("mov.b64 %0, {%1, %1};" : "=l"(r) : "r"(u));
    return r;
}
__device__ __forceinline__ void fma2(ull& d, ull a, ull b) {
    asm("fma.rn.f32x2 %0, %1, %2, %0;" : "+l"(d) : "l"(a), "l"(b));
}
__device__ __forceinline__ float2 unp(ull v) {
    float2 f;
    asm("mov.b64 {%0, %1}, %2;" : "=f"(f.x), "=f"(f.y) : "l"(v));
    return f;
}

// =============== forward (R3-proven): H = tanh(In@W1+b1), S = 1-H^2 ===============
__global__ void fwd_all(const float* __restrict__ X, const float* __restrict__ Z,
                        const float* __restrict__ T, const float* __restrict__ W1,
                        const float* __restrict__ b1) {
    __shared__ __align__(16) float As[16][68];
    __shared__ __align__(16) float Bs[16][68];
    const int tid = threadIdx.x;
    const int rb = blockIdx.y, nb = blockIdx.x;
    const float* src; float* Hd; float* Sd; int row0;
    if (rb < 16)      { src = X; Hd = g_HX; Sd = g_SX; row0 = rb*64; }
    else if (rb < 18) { src = Z; Hd = g_HZ; Sd = g_SZ; row0 = (rb-16)*64; }
    else              { src = T; Hd = g_HT; Sd = g_ST; row0 = (rb-18)*64; }
    const int lrow = tid >> 1, lk = (tid & 1) << 3;
    const int kr = tid >> 3, nq = (tid & 7) << 3;
    const int tx = tid & 15, ty = tid >> 4;
    float acc[8][4] = {};
    for (int k0 = 0; k0 < D_IN; k0 += 16) {
        float4 a0 = *(const float4*)&src[(row0+lrow)*D_IN + k0 + lk];
        float4 a1 = *(const float4*)&src[(row0+lrow)*D_IN + k0 + lk + 4];
        float4 b0 = *(const float4*)&W1[(k0+kr)*H_DIM + nb*64 + nq];
        float4 b1v= *(const float4*)&W1[(k0+kr)*H_DIM + nb*64 + nq + 4];
        __syncthreads();
        As[lk+0][lrow]=a0.x; As[lk+1][lrow]=a0.y; As[lk+2][lrow]=a0.z; As[lk+3][lrow]=a0.w;
        As[lk+4][lrow]=a1.x; As[lk+5][lrow]=a1.y; As[lk+6][lrow]=a1.z; As[lk+7][lrow]=a1.w;
        *(float4*)&Bs[kr][nq] = b0; *(float4*)&Bs[kr][nq+4] = b1v;
        __syncthreads();
        #pragma unroll
        for (int kk = 0; kk < 16; ++kk) {
            float4 a4 = *(const float4*)&As[kk][ty*8];
            float4 a5 = *(const float4*)&As[kk][ty*8+4];
            float4 b4 = *(const float4*)&Bs[kk][tx*4];
            float a[8] = {a4.x,a4.y,a4.z,a4.w,a5.x,a5.y,a5.z,a5.w};
            float b[4] = {b4.x,b4.y,b4.z,b4.w};
            #pragma unroll
            for (int u = 0; u < 8; ++u)
                #pragma unroll
                for (int v = 0; v < 4; ++v) acc[u][v] = fmaf(a[u], b[v], acc[u][v]);
        }
    }
    const int n0 = nb*64 + tx*4;
    float4 bv = *(const float4*)&b1[n0];
    #pragma unroll
    for (int u = 0; u < 8; ++u) {
        int m = row0 + ty*8 + u;
        float4 h4, s4;
        h4.x = tanhf(acc[u][0]+bv.x); h4.y = tanhf(acc[u][1]+bv.y);
        h4.z = tanhf(acc[u][2]+bv.z); h4.w = tanhf(acc[u][3]+bv.w);
        s4.x = 1.f-h4.x*h4.x; s4.y = 1.f-h4.y*h4.y;
        s4.z = 1.f-h4.z*h4.z; s4.w = 1.f-h4.w*h4.w;
        *(float4*)&Hd[m*H_DIM + n0] = h4;
        *(float4*)&Sd[m*H_DIM + n0] = s4;
    }
}

// =============== lambda1 = F + Y ; side-job: w2sq table ===============
__global__ void lam_kernel(const float* __restrict__ Y, const float* __restrict__ W2,
                           const float* __restrict__ b2) {
    int tid = threadIdx.x;
    int idx = blockIdx.x*256 + tid;
    if (idx < H_DIM*C_OUT) {
        int k = idx / C_OUT, i = idx - k*C_OUT;
        float w = W2[idx];
        g_W2SQ[i*H_DIM + k] = w*w;
    }
    int warp = tid >> 5, lane = tid & 31;
    int row = blockIdx.x * 8 + warp;
    float h[12];
    #pragma unroll
    for (int r = 0; r < 12; ++r) h[r] = g_HX[row*H_DIM + lane + r*32];
    #pragma unroll
    for (int c = 0; c < C_OUT; ++c) {
        float acc = 0.f;
        #pragma unroll
        for (int r = 0; r < 12; ++r) acc += h[r] * W2[(lane + r*32)*C_OUT + c];
        #pragma unroll
        for (int o = 16; o; o >>= 1) acc += __shfl_down_sync(0xffffffffu, acc, o);
        if (lane == 0) g_LAM[row*C_OUT + c] = acc + b2[c] + Y[row*C_OUT + c];
    }
}

// =============== Pcat/Qcat [128 x 1408] (cols = X|Z|T), R3-proven inner ===============
__global__ void pqcat(const float* __restrict__ X, const float* __restrict__ Z,
                      const float* __restrict__ T) {
    __shared__ __align__(16) float As[16][68];
    __shared__ __align__(16) float Bs[16][68];
    const int tid = threadIdx.x;
    int j = blockIdx.x;
    const int isQ = (j >= 44); if (isQ) j -= 44;
    const int mt = j / 22, nt = j - (j/22)*22;
    const float *Ap, *Bp; int K;
    if (!isQ) {
        Ap = g_HZ; K = H_DIM;
        Bp = (nt < 16) ? (g_HX + nt*64*H_DIM)
           : (nt < 18) ? (g_HZ + (nt-16)*64*H_DIM)
                       : (g_HT + (nt-18)*64*H_DIM);
    } else {
        Ap = Z; K = D_IN;
        Bp = (nt < 16) ? (X + nt*64*D_IN)
           : (nt < 18) ? (Z + (nt-16)*64*D_IN)
                       : (T + (nt-18)*64*D_IN);
    }
    float* outp = isQ ? g_Qcat : g_Pcat;
    const int bm = mt*64;
    const int lrow = tid >> 1, lk = (tid & 1) << 3;
    const int tx = tid & 15, ty = tid >> 4;
    float acc[8][4] = {};
    for (int k0 = 0; k0 < K; k0 += 16) {
        float4 a0 = *(const float4*)&Ap[(bm+lrow)*K + k0 + lk];
        float4 a1 = *(const float4*)&Ap[(bm+lrow)*K + k0 + lk + 4];
        float4 b0 = *(const float4*)&Bp[lrow*K + k0 + lk];
        float4 b1 = *(const float4*)&Bp[lrow*K + k0 + lk + 4];
        __syncthreads();
        As[lk+0][lrow]=a0.x; As[lk+1][lrow]=a0.y; As[lk+2][lrow]=a0.z; As[lk+3][lrow]=a0.w;
        As[lk+4][lrow]=a1.x; As[lk+5][lrow]=a1.y; As[lk+6][lrow]=a1.z; As[lk+7][lrow]=a1.w;
        Bs[lk+0][lrow]=b0.x; Bs[lk+1][lrow]=b0.y; Bs[lk+2][lrow]=b0.z; Bs[lk+3][lrow]=b0.w;
        Bs[lk+4][lrow]=b1.x; Bs[lk+5][lrow]=b1.y; Bs[lk+6][lrow]=b1.z; Bs[lk+7][lrow]=b1.w;
        __syncthreads();
        #pragma unroll
        for (int kk = 0; kk < 16; ++kk) {
            float4 a4 = *(const float4*)&As[kk][ty*8];
            float4 a5 = *(const float4*)&As[kk][ty*8+4];
            float4 b4 = *(const float4*)&Bs[kk][tx*4];
            float a[8] = {a4.x,a4.y,a4.z,a4.w,a5.x,a5.y,a5.z,a5.w};
            float b[4] = {b4.x,b4.y,b4.z,b4.w};
            #pragma unroll
            for (int u = 0; u < 8; ++u)
                #pragma unroll
                for (int v = 0; v < 4; ++v) acc[u][v] = fmaf(a[u], b[v], acc[u][v]);
        }
    }
    const int n0 = nt*64 + tx*4;
    #pragma unroll
    for (int u = 0; u < 8; ++u) {
        int m = bm + ty*8 + u;
        float4 o4 = {acc[u][0]+1.f, acc[u][1]+1.f, acc[u][2]+1.f, acc[u][3]+1.f};
        *(float4*)&outp[m*NCAT + n0] = o4;
    }
}

// =============== kstack: all 30 kernel matrices as one GEMM ===============
// C[i][m][n] = SCALE*(Pcat[m][n] + Qcat[m][n] * ((SZ w_i^2) @ Bsrc^T)[m][n])
// grid (11, 10), 256 threads, 128x128 tile, 8x8/thread FFMA2
__global__ void __launch_bounds__(256, 2)
kstack() {
    __shared__ __align__(16) float As[16][132];
    __shared__ __align__(16) float Bs[16][132];
    const int tid = threadIdx.x;
    const int i = blockIdx.y, nb = blockIdx.x;
    const float* Bsrc;
    if (nb < 8)       Bsrc = g_SX + nb*128*H_DIM;
    else if (nb == 8) Bsrc = g_SZ;
    else              Bsrc = g_ST + (nb-9)*128*H_DIM;
    const int lr = tid >> 1, lq = (tid & 1) << 3;
    const int ty = tid >> 4, tx = tid & 15;
    const float* wrow = g_W2SQ + i*H_DIM;
    ull acc[8][4] = {};
    for (int k0 = 0; k0 < H_DIM; k0 += 16) {
        float4 a0 = *(const float4*)&g_SZ[lr*H_DIM + k0 + lq];
        float4 a1 = *(const float4*)&g_SZ[lr*H_DIM + k0 + lq + 4];
        float4 b0 = *(const float4*)&Bsrc[lr*H_DIM + k0 + lq];
        float4 b1 = *(const float4*)&Bsrc[lr*H_DIM + k0 + lq + 4];
        float4 w0 = *(const float4*)&wrow[k0 + lq];
        float4 w1 = *(const float4*)&wrow[k0 + lq + 4];
        __syncthreads();
        As[lq+0][lr]=a0.x*w0.x; As[lq+1][lr]=a0.y*w0.y; As[lq+2][lr]=a0.z*w0.z; As[lq+3][lr]=a0.w*w0.w;
        As[lq+4][lr]=a1.x*w1.x; As[lq+5][lr]=a1.y*w1.y; As[lq+6][lr]=a1.z*w1.z; As[lq+7][lr]=a1.w*w1.w;
        Bs[lq+0][lr]=b0.x; Bs[lq+1][lr]=b0.y; Bs[lq+2][lr]=b0.z; Bs[lq+3][lr]=b0.w;
        Bs[lq+4][lr]=b1.x; Bs[lq+5][lr]=b1.y; Bs[lq+6][lr]=b1.z; Bs[lq+7][lr]=b1.w;
        __syncthreads();
        #pragma unroll
        for (int kk = 0; kk < 16; ++kk) {
            float4 a4 = *(const float4*)&As[kk][ty*8];
            float4 a5 = *(const float4*)&As[kk][ty*8+4];
            ull b[4];
            #pragma unroll
            for (int v = 0; v < 4; ++v) b[v] = *(const ull*)&Bs[kk][tx*8 + v*2];
            float a[8] = {a4.x,a4.y,a4.z,a4.w,a5.x,a5.y,a5.z,a5.w};
            #pragma unroll
            for (int u = 0; u < 8; ++u) {
                ull du = dup2(a[u]);
                #pragma unroll
                for (int v = 0; v < 4; ++v) fma2(acc[u][v], du, b[v]);
            }
        }
    }
    const int nloc = tx*8;                 // 0..120 within the 128-col tile
    const int nglob = nb*128 + nloc;
    #pragma unroll
    for (int u = 0; u < 8; ++u) {
        const int m = ty*8 + u;
        float4 p0 = *(const float4*)&g_Pcat[m*NCAT + nglob];
        float4 p1 = *(const float4*)&g_Pcat[m*NCAT + nglob + 4];
        float4 q0 = *(const float4*)&g_Qcat[m*NCAT + nglob];
        float4 q1 = *(const float4*)&g_Qcat[m*NCAT + nglob + 4];
        float pp[8] = {p0.x,p0.y,p0.z,p0.w,p1.x,p1.y,p1.z,p1.w};
        float qq[8] = {q0.x,q0.y,q0.z,q0.w,q1.x,q1.y,q1.z,q1.w};
        float o[8];
        #pragma unroll
        for (int v = 0; v < 4; ++v) {
            float2 uu = unp(acc[u][v]);
            o[v*2]   = SCALE_K * (pp[v*2]   + qq[v*2]  *uu.x);
            o[v*2+1] = SCALE_K * (pp[v*2+1] + qq[v*2+1]*uu.y);
        }
        if (nb < 8) {
            float* dst = g_Kzx + (size_t)i*M_IND*N_DATA + (size_t)m*N_DATA + nb*128 + nloc;
            *(float4*)dst     = make_float4(o[0],o[1],o[2],o[3]);
            *(float4*)(dst+4) = make_float4(o[4],o[5],o[6],o[7]);
        } else if (nb == 8) {
            #pragma unroll
            for (int c = 0; c < 8; ++c) if (m == nloc + c) o[c] += JITTER_K;
            float* dst = g_Kzz + (size_t)i*M_IND*M_IND + m*M_IND + nloc;
            *(float4*)dst     = make_float4(o[0],o[1],o[2],o[3]);
            *(float4*)(dst+4) = make_float4(o[4],o[5],o[6],o[7]);
        } else {
            const int t0 = (nb-9)*128 + nloc;
            #pragma unroll
            for (int c = 0; c < 8; ++c)
                g_Ktz[(size_t)i*NT_PTS*M_IND + (t0+c)*M_IND + m] = o[c];
        }
    }
}

// =============== Bpart (split-K=8 of 2*Kzx@Kzx^T) + alpha ===============
__global__ void __launch_bounds__(256, 2)
bgemm_alpha() {
    const int tid = threadIdx.x;
    const int j = blockIdx.x;
    if (j < 80) {
        __shared__ __align__(16) float As[16][132];
        const int i = j >> 3, kc = j & 7;
        const float* A = g_Kzx + (size_t)i*M_IND*N_DATA;
        const int kbeg = kc*128;
        const int lr = tid >> 1, lq = (tid & 1) << 3;
        const int ty = tid >> 4, tx = tid & 15;
        ull acc[8][4] = {};
        for (int k0 = kbeg; k0 < kbeg+128; k0 += 16) {
            float4 a0 = *(const float4*)&A[lr*N_DATA + k0 + lq];
            float4 a1 = *(const float4*)&A[lr*N_DATA + k0 + lq + 4];
            __syncthreads();
            As[lq+0][lr]=a0.x; As[lq+1][lr]=a0.y; As[lq+2][lr]=a0.z; As[lq+3][lr]=a0.w;
            As[lq+4][lr]=a1.x; As[lq+5][lr]=a1.y; As[lq+6][lr]=a1.z; As[lq+7][lr]=a1.w;
            __syncthreads();
            #pragma unroll
            for (int kk = 0; kk < 16; ++kk) {
                float4 a4 = *(const float4*)&As[kk][ty*8];
                float4 a5 = *(const float4*)&As[kk][ty*8+4];
                ull b[4];
                #pragma unroll
                for (int v = 0; v < 4; ++v) b[v] = *(const ull*)&As[kk][tx*8 + v*2];
                float a[8] = {a4.x,a4.y,a4.z,a4.w,a5.x,a5.y,a5.z,a5.w};
                #pragma unroll
                for (int u = 0; u < 8; ++u) {
                    ull du = dup2(a[u]);
                    #pragma unroll
                    for (int v = 0; v < 4; ++v) fma2(acc[u][v], du, b[v]);
                }
            }
        }
        float* outp = g_Bpart + (size_t)(kc*C_OUT + i)*M_IND*M_IND;
        const int n0 = tx*8;
        #pragma unroll
        for (int u = 0; u < 8; ++u) {
            int m = ty*8 + u;
            float o[8];
            #pragma unroll
            for (int v = 0; v < 4; ++v) {
                float2 pp = unp(acc[u][v]);
                o[v*2] = 2.f*pp.x; o[v*2+1] = 2.f*pp.y;
            }
            *(float4*)&outp[m*M_IND + n0]   = make_float4(o[0],o[1],o[2],o[3]);
            *(float4*)&outp[m*M_IND + n0+4] = make_float4(o[4],o[5],o[6],o[7]);
        }
    } else {
        const int k = j - 80;
        const int w = tid >> 5, lane = tid & 31;
        const int gw = k*8 + w;            // 0..159
        const int i = gw >> 4, rb = (gw & 15) * 8;
        #pragma unroll
        for (int rr = 0; rr < 8; ++rr) {
            int m = rb + rr;
            const float* row = g_Kzx + ((size_t)i*M_IND + m)*N_DATA;
            float acc = 0.f;
            for (int n = lane; n < N_DATA; n += 32) acc += row[n] * g_LAM[n*C_OUT + i];
            #pragma unroll
            for (int o = 16; o; o >>= 1) acc += __shfl_down_sync(0xffffffffu, acc, o);
            if (lane == 0) g_alpha[i*M_IND + m] = acc;
        }
    }
}

// =============== batched Cholesky of Kzz and B = Kzz + sum(Bpart) ===============
__global__ void chol_all() {
    const int s = blockIdx.x, tid = threadIdx.x;
    const int isB = (s >= C_OUT);
    const int i = isB ? s - C_OUT : s;
    const float* A0 = g_Kzz + (size_t)i*M_IND*M_IND;
    __shared__ float L[LPACK];
    __shared__ float s_diag;
    for (int r = 0; r < M_IND; ++r)
        for (int c = tid; c <= r; c += 256) {
            float v = A0[r*M_IND + c];
            if (isB) {
                #pragma unroll
                for (int p = 0; p < 8; ++p)
                    v += g_Bpart[((size_t)(p*C_OUT + i)*M_IND + r)*M_IND + c];
            }
            L[((r*(r+1))>>1) + c] = v;
        }
    __syncthreads();
    for (int jc = 0; jc < M_IND; ++jc) {
        int ir = jc + tid;
        float sum = 0.f;
        if (ir < M_IND) {
            const float* ri = &L[(ir*(ir+1)) >> 1];
            const float* rj = &L[(jc*(jc+1)) >> 1];
            float s0=0,s1=0,s2=0,s3=0; int k = 0;
            for (; k+4 <= jc; k += 4) {
                s0 += ri[k]*rj[k];     s1 += ri[k+1]*rj[k+1];
                s2 += ri[k+2]*rj[k+2]; s3 += ri[k+3]*rj[k+3];
            }
            for (; k < jc; ++k) s0 += ri[k]*rj[k];
            sum = ri[jc] - ((s0+s1)+(s2+s3));
            if (tid == 0) s_diag = sum;
        }
        __syncthreads();
        float d = sqrtf(s_diag);
        if (ir < M_IND) L[((ir*(ir+1))>>1) + jc] = (tid == 0) ? d : (sum / d);
        __syncthreads();
    }
    float* out = isB ? (g_LB + i*LPACK) : (g_LKzz + i*LPACK);
    for (int idx = tid; idx < LPACK; idx += 256) out[idx] = L[idx];
}

// =============== solves: 640 fs blocks + 10 meansolve blocks ===============
__global__ void solve_all() {
    __shared__ float Lp[LPACK];
    __shared__ float dinv[M_IND];
    __shared__ float ysm[M_IND];
    const int b = blockIdx.x, tid = threadIdx.x;
    const int w = tid >> 5, lane = tid & 31;
    if (b < 640) {
        const int s = b >> 5;
        const int t = (b & 31)*8 + w;
        const int i = (s < C_OUT) ? s : s - C_OUT;
        const float* Ls = (s < C_OUT) ? (g_LKzz + s*LPACK) : (g_LB + (s-C_OUT)*LPACK);
        for (int idx = tid; idx < LPACK; idx += 256) Lp[idx] = Ls[idx];
        if (tid < M_IND) dinv[tid] = 1.0f / Ls[((tid*(tid+1))>>1) + tid];
        __syncthreads();
        const float* bvec = g_Ktz + ((size_t)i*NT_PTS + t)*M_IND;
        float br[4]; int base[4];
        #pragma unroll
        for (int r = 0; r < 4; ++r) {
            br[r] = bvec[lane + 32*r];
            int row = r*32 + lane;
            base[r] = (row*(row+1)) >> 1;
        }
        float ss = 0.f;
        #pragma unroll
        for (int oreg = 0; oreg < 4; ++oreg) {
            for (int jj = 0; jj < 32; ++jj) {
                int jc = oreg*32 + jj;
                float yj = __shfl_sync(0xffffffffu, br[oreg], jj) * dinv[jc];
                ss = fmaf(yj, yj, ss);
                if (lane > jj) br[oreg] -= Lp[base[oreg] + jc] * yj;
                #pragma unroll
                for (int r = oreg+1; r < 4; ++r) br[r] -= Lp[base[r] + jc] * yj;
            }
        }
        if (lane == 0) {
            if (s < C_OUT) g_SSZ[i*NT_PTS + t] = ss;
            else           g_SSB[i*NT_PTS + t] = ss;
        }
    } else {
        const int i = b - 640;
        const float* Ls = g_LB + i*LPACK;
        for (int idx = tid; idx < LPACK; idx += 256) Lp[idx] = Ls[idx];
        if (tid < M_IND) dinv[tid] = 1.0f / Ls[((tid*(tid+1))>>1) + tid];
        __syncthreads();
        if (w != 0) return;
        float br[4]; int base[4];
        #pragma unroll
        for (int r = 0; r < 4; ++r) {
            br[r] = g_alpha[i*M_IND + lane + 32*r];
            int row = r*32 + lane;
            base[r] = (row*(row+1)) >> 1;
        }
        #pragma unroll
        for (int oreg = 0; oreg < 4; ++oreg) {
            for (int jj = 0; jj < 32; ++jj) {
                int jc = oreg*32 + jj;
                float yj = __shfl_sync(0xffffffffu, br[oreg], jj) * dinv[jc];
                if (lane == 0) ysm[jc] = yj;
                if (lane > jj) br[oreg] -= Lp[base[oreg] + jc] * yj;
                #pragma unroll
                for (int r = oreg+1; r < 4; ++r) br[r] -= Lp[base[r] + jc] * yj;
            }
        }
        __syncwarp();
        float xr[4];
        #pragma unroll
        for (int r = 0; r < 4; ++r) xr[r] = ysm[r*32 + lane];
        #pragma unroll
        for (int oreg = 3; oreg >= 0; --oreg) {
            for (int jj = 31; jj >= 0; --jj) {
                int jc = oreg*32 + jj;
                float xj = __shfl_sync(0xffffffffu, xr[oreg], jj) * dinv[jc];
                if (lane == 0) g_cvec[i*M_IND + jc] = xj;
                int rb2 = (jc*(jc+1)) >> 1;
                if (lane < jj) xr[oreg] -= Lp[rb2 + oreg*32 + lane] * xj;
                #pragma unroll
                for (int r = 0; r < 4; ++r)
                    if (r < oreg) xr[r] -= Lp[rb2 + r*32 + lane] * xj;
            }
        }
    }
}

// =============== epilogue: mean + variance ===============
__global__ void epilogue(const float* __restrict__ Xt, const float* __restrict__ W2,
                         float* __restrict__ out) {
    const int gw = blockIdx.x*8 + (threadIdx.x >> 5);
    const int lane = threadIdx.x & 31;
    const int t = gw / C_OUT, i = gw - t*C_OUT;
    float accU = 0.f, ph = 0.f, qx = 0.f;
    for (int k = lane; k < H_DIM; k += 32) {
        float s = g_ST[t*H_DIM + k];
        float h = g_HT[t*H_DIM + k];
        float w = W2[k*C_OUT + i];
        accU = fmaf(s*s, w*w, accU);
        ph = fmaf(h, h, ph);
    }
    for (int k = lane; k < D_IN; k += 32) { float x = Xt[t*D_IN + k]; qx = fmaf(x, x, qx); }
    float mean = 0.f;
    const float* kr = g_Ktz + ((size_t)i*NT_PTS + t)*M_IND;
    const float* cr = g_cvec + i*M_IND;
    #pragma unroll
    for (int r = 0; r < 4; ++r) mean += kr[lane + 32*r] * cr[lane + 32*r];
    #pragma unroll
    for (int o = 16; o; o >>= 1) {
        accU += __shfl_xor_sync(0xffffffffu, accU, o);
        ph   += __shfl_xor_sync(0xffffffffu, ph, o);
        qx   += __shfl_xor_sync(0xffffffffu, qx, o);
        mean += __shfl_xor_sync(0xffffffffu, mean, o);
    }
    if (lane == 0) {
        float kttd = SCALE_K * ((ph + 1.f) + (qx + 1.f)*accU);
        out[t*C_OUT + i] = mean;
        out[NT_PTS*C_OUT + t*C_OUT + i] = kttd - g_SSZ[i*NT_PTS + t] + g_SSB[i*NT_PTS + t];
    }
}

extern "C" void kernel_launch(void* const* d_in, const int* in_sizes, int n_in,
                              void* d_out, int out_size) {
    const float* X  = (const float*)d_in[0];
    const float* Y  = (const float*)d_in[1];
    const float* Z  = (const float*)d_in[2];
    const float* Xt = (const float*)d_in[3];
    const float* W1 = (const float*)d_in[4];
    const float* b1 = (const float*)d_in[5];
    const float* W2 = (const float*)d_in[6];
    const float* b2 = (const float*)d_in[7];
    float* out = (float*)d_out;

    fwd_all<<<dim3(6,22), 128>>>(X, Z, Xt, W1, b1);
    lam_kernel<<<128, 256>>>(Y, W2, b2);
    pqcat<<<88, 128>>>(X, Z, Xt);
    kstack<<<dim3(11,10), 256>>>();
    bgemm_alpha<<<100, 256>>>();
    chol_all<<<20, 256>>>();
    solve_all<<<650, 256>>>();
    epilogue<<<320, 256>>>(Xt, W2, out);
}